// round 11
// baseline (speedup 1.0000x reference)
#include <cuda_runtime.h>
#include <cuda_fp16.h>
#include <math.h>

#define N_NODES 100000
#define E_EDGES 3200000
#define F_IN    500
#define HID     64
#define CCH     64
#define KFREQ   5
#define DORD    10

#define PGRID   148            // persistent blocks; GB300 has 152 SMs, 1 block/SM
#define ROWS_PB ((N_NODES + PGRID - 1) / PGRID)   // 676
#define PSMEM   (ROWS_PB * 32 * sizeof(float2))   // 173,056 B

// ---------------- scratch (static device globals; no allocation) ----------------
__device__ __align__(16) float  g_xh[N_NODES * HID];     // relu(feature@W1+b1)
__device__ __align__(16) float  g_xc[N_NODES * CCH];     // lin2 output fp32
__device__ __align__(16) __half g_xc16[N_NODES * CCH];   // u1 = dinv*xc (fp16, hop-1 input)
__device__ __align__(16) __half g_h16A[N_NODES * CCH];   // fp16 scaled-state ping (odd-d out)
__device__ __align__(16) __half g_h16B[N_NODES * CCH];   // fp16 scaled-state pong (even-d out)
__device__ __align__(16) float  g_hidden[N_NODES * CCH]; // fp32 accumulator (init c0*xc)
__device__ int    g_src[E_EDGES];                        // CSR-by-dst: src per edge
__device__ int    g_deg[N_NODES];
__device__ int    g_indeg[N_NODES];
__device__ float  g_dinv[N_NODES];
__device__ int    g_rowptr[N_NODES + 1];
__device__ int    g_cursor[N_NODES + 1];
__device__ int    g_tmp[N_NODES];
__device__ int    g_btot[128];
__device__ int    g_boff[128];
__device__ float  g_coeff[16];
__device__ volatile unsigned g_bar_gen;
__device__ unsigned g_bar_count;

// ---------------- small utility kernels ----------------
__global__ void zero_counts_kernel() {
    int i = blockIdx.x * blockDim.x + threadIdx.x;
    if (i < N_NODES) { g_deg[i] = 0; g_indeg[i] = 0; }
    if (i == 0) { g_bar_count = 0; g_bar_gen = 0; }
}

// coeff[d] = sum_k alpha[k]*SINC[k][d] + beta[k]*COSC[k][d] (tables in fp64, cast)
__global__ void coeff_kernel(const float* __restrict__ alpha,
                             const float* __restrict__ beta) {
    int d = threadIdx.x;
    if (d > DORD) return;
    float acc = 0.0f;
    for (int k = 0; k < KFREQ; ++k) {
        double x = (double)(k + 1) * 3.14159265358979323846;
        double p = 1.0;
        for (int i = 0; i < d; ++i) p *= x;
        double f = 1.0;
        for (int i = 2; i <= d; ++i) f *= (double)i;
        double sinc = 0.0, cosc = 0.0;
        if ((d & 1) == 0) {
            double sgn = (((d / 2) & 1) == 0) ? 1.0 : -1.0;
            cosc = sgn * p / f;
        } else {
            double sgn = ((((d - 1) / 2) & 1) == 0) ? 1.0 : -1.0;
            sinc = sgn * p / f;
        }
        acc += alpha[k] * (float)sinc + beta[k] * (float)cosc;
    }
    g_coeff[d] = acc;
}

// edges buffer is int32 (jax x64 disabled)
__global__ void pass1_kernel(const int* __restrict__ edges) {
    int e = blockIdx.x * blockDim.x + threadIdx.x;
    if (e >= E_EDGES) return;
    int s = edges[e];
    int d = edges[E_EDGES + e];
    if (s != d && (unsigned)s < N_NODES && (unsigned)d < N_NODES) {
        atomicAdd(&g_deg[s], 1);
        atomicAdd(&g_indeg[d], 1);
    }
}

__global__ void dinv_kernel() {
    int i = blockIdx.x * blockDim.x + threadIdx.x;
    if (i >= N_NODES) return;
    int dg = g_deg[i];
    g_dinv[i] = (dg > 0) ? rsqrtf((float)dg) : 0.0f;
}

// ------- exclusive scan of g_indeg -> g_rowptr -------
__global__ void scan1_kernel(int n) {
    __shared__ int s[1024];
    int i = blockIdx.x * 1024 + threadIdx.x;
    int v = (i < n) ? g_indeg[i] : 0;
    s[threadIdx.x] = v;
    __syncthreads();
    for (int off = 1; off < 1024; off <<= 1) {
        int t = (threadIdx.x >= off) ? s[threadIdx.x - off] : 0;
        __syncthreads();
        s[threadIdx.x] += t;
        __syncthreads();
    }
    if (i < n) g_tmp[i] = s[threadIdx.x];
    if (threadIdx.x == 1023) g_btot[blockIdx.x] = s[1023];
}

__global__ void scan2_kernel(int nb) {
    if (threadIdx.x == 0 && blockIdx.x == 0) {
        int run = 0;
        for (int b = 0; b < nb; ++b) { g_boff[b] = run; run += g_btot[b]; }
    }
}

__global__ void scan3_kernel(int n) {
    int i = blockIdx.x * 1024 + threadIdx.x;
    if (i < n) {
        int v = g_tmp[i] + g_boff[blockIdx.x];
        g_rowptr[i + 1] = v;
        if (i + 1 < N_NODES) g_cursor[i + 1] = v;
        if (i == 0) { g_rowptr[0] = 0; g_cursor[0] = 0; }
    }
}

__global__ void scatter_kernel(const int* __restrict__ edges) {
    int e = blockIdx.x * blockDim.x + threadIdx.x;
    if (e >= E_EDGES) return;
    int s = edges[e];
    int d = edges[E_EDGES + e];
    if (s != d && (unsigned)s < N_NODES && (unsigned)d < N_NODES) {
        int pos = atomicAdd(&g_cursor[d], 1);
        g_src[pos] = s;
    }
}

// ---------------- packed f32x2 FMA helper ----------------
__device__ __forceinline__ void ffma2(unsigned long long& acc,
                                      unsigned long long a,
                                      unsigned long long b) {
    asm("fma.rn.f32x2 %0, %1, %2, %0;" : "+l"(acc) : "l"(a), "l"(b));
}
__device__ __forceinline__ float2 unpack2(unsigned long long p) {
    float2 r;
    asm("mov.b64 {%0, %1}, %2;" : "=f"(r.x), "=f"(r.y) : "l"(p));
    return r;
}

// ---------------- GEMM1: xh = relu(feature @ W1 + b1) ----------------
__global__ __launch_bounds__(256) void gemm1_kernel(const float* __restrict__ feat,
                                                    const float* __restrict__ W1,
                                                    const float* __restrict__ b1) {
    __shared__ __align__(16) float2 As2[16 * 65];
    __shared__ __align__(16) float  Ws[16 * 64];
    int tid = threadIdx.x;
    int tx = tid & 15, ty = tid >> 4;
    int row0 = blockIdx.x * 64;
    int kkA = tid & 15;
    int rA = (tid >> 4) * 4;
    unsigned long long acc[4][2] = {};

    for (int k0 = 0; k0 < F_IN; k0 += 16) {
        bool kok = (k0 + kkA) < F_IN;
#pragma unroll
        for (int i = 0; i < 4; ++i) {
            int r = row0 + rA + i;
            float v = 0.0f;
            if (r < N_NODES && kok) v = __ldcs(&feat[r * F_IN + k0 + kkA]);
            As2[kkA * 65 + rA + i] = make_float2(v, v);
        }
        {
            int L = tid * 4;
            int kk = L >> 6;
            int n = L & 63;
            float4 w4 = make_float4(0.f, 0.f, 0.f, 0.f);
            if (k0 + kk < F_IN) w4 = *(const float4*)&W1[(k0 + kk) * HID + n];
            *(float4*)&Ws[kk * 64 + n] = w4;
        }
        __syncthreads();
#pragma unroll
        for (int kk = 0; kk < 16; ++kk) {
            ulonglong2 bp = *(const ulonglong2*)&Ws[kk * 64 + tx * 4];
            const unsigned long long* ap =
                (const unsigned long long*)&As2[kk * 65 + ty * 4];
#pragma unroll
            for (int i = 0; i < 4; ++i) {
                unsigned long long a = ap[i];
                ffma2(acc[i][0], a, bp.x);
                ffma2(acc[i][1], a, bp.y);
            }
        }
        __syncthreads();
    }
#pragma unroll
    for (int i = 0; i < 4; ++i) {
        int r = row0 + ty * 4 + i;
        if (r >= N_NODES) continue;
        float2 p0 = unpack2(acc[i][0]);
        float2 p1 = unpack2(acc[i][1]);
        int c = tx * 4;
        g_xh[r * HID + c + 0] = fmaxf(p0.x + __ldg(&b1[c + 0]), 0.0f);
        g_xh[r * HID + c + 1] = fmaxf(p0.y + __ldg(&b1[c + 1]), 0.0f);
        g_xh[r * HID + c + 2] = fmaxf(p1.x + __ldg(&b1[c + 2]), 0.0f);
        g_xh[r * HID + c + 3] = fmaxf(p1.y + __ldg(&b1[c + 3]), 0.0f);
    }
}

// ---------------- GEMM2: xc = xh @ W2 + b2 ; hidden = c0*xc ; xc16 = dinv*xc ----------------
__global__ __launch_bounds__(256) void gemm2_kernel(const float* __restrict__ W2,
                                                    const float* __restrict__ b2) {
    __shared__ __align__(16) float2 As2[16 * 65];
    __shared__ __align__(16) float  Ws[16 * 64];
    int tid = threadIdx.x;
    int tx = tid & 15, ty = tid >> 4;
    int row0 = blockIdx.x * 64;
    int kkA = tid & 15;
    int rA = (tid >> 4) * 4;
    unsigned long long acc[4][2] = {};

    for (int k0 = 0; k0 < HID; k0 += 16) {
#pragma unroll
        for (int i = 0; i < 4; ++i) {
            int r = row0 + rA + i;
            float v = 0.0f;
            if (r < N_NODES) v = g_xh[r * HID + k0 + kkA];
            As2[kkA * 65 + rA + i] = make_float2(v, v);
        }
        {
            int L = tid * 4;
            int kk = L >> 6;
            int n = L & 63;
            float4 w4 = *(const float4*)&W2[(k0 + kk) * CCH + n];
            *(float4*)&Ws[kk * 64 + n] = w4;
        }
        __syncthreads();
#pragma unroll
        for (int kk = 0; kk < 16; ++kk) {
            ulonglong2 bp = *(const ulonglong2*)&Ws[kk * 64 + tx * 4];
            const unsigned long long* ap =
                (const unsigned long long*)&As2[kk * 65 + ty * 4];
#pragma unroll
            for (int i = 0; i < 4; ++i) {
                unsigned long long a = ap[i];
                ffma2(acc[i][0], a, bp.x);
                ffma2(acc[i][1], a, bp.y);
            }
        }
        __syncthreads();
    }
    float c0 = g_coeff[0];
#pragma unroll
    for (int i = 0; i < 4; ++i) {
        int r = row0 + ty * 4 + i;
        if (r >= N_NODES) continue;
        float2 p0 = unpack2(acc[i][0]);
        float2 p1 = unpack2(acc[i][1]);
        int c = tx * 4;
        float v0 = p0.x + __ldg(&b2[c + 0]);
        float v1 = p0.y + __ldg(&b2[c + 1]);
        float v2 = p1.x + __ldg(&b2[c + 2]);
        float v3 = p1.y + __ldg(&b2[c + 3]);
        float* xr = &g_xc[r * CCH + c];
        xr[0] = v0; xr[1] = v1; xr[2] = v2; xr[3] = v3;
        float* hr = &g_hidden[r * CCH + c];
        hr[0] = c0 * v0; hr[1] = c0 * v1; hr[2] = c0 * v2; hr[3] = c0 * v3;
        float di = __ldg(&g_dinv[r]);       // scaled state u1 = dinv * xc
        __half2* x16 = (__half2*)&g_xc16[r * CCH + c];
        x16[0] = __floats2half2_rn(di * v0, di * v1);
        x16[1] = __floats2half2_rn(di * v2, di * v3);
    }
}

// ---------------- persistent diffusion kernel ----------------
// Software grid barrier (generation counter). Co-residency guaranteed:
// 148 blocks, 1024 thr + 173KB smem => exactly 1 block/SM, GB300 has 152 SMs.
__device__ __forceinline__ void grid_barrier() {
    __syncthreads();
    if (threadIdx.x == 0) {
        __threadfence();
        unsigned gen = g_bar_gen;
        if (atomicInc(&g_bar_count, PGRID - 1) == PGRID - 1) {
            g_bar_gen = gen + 1;           // release
        } else {
            while (g_bar_gen == gen) __nanosleep(64);
        }
        __threadfence();
    }
    __syncthreads();
}

// sum of scaled state u over the row's sources. __ldcg: L2-only — L1 is NOT
// flushed inside a persistent kernel, plain __ldg could return stale ping-pong data.
__device__ __forceinline__ float2 row_gather(const __half2* __restrict__ tin,
                                             int beg, int end, int lane) {
    float2 acc = make_float2(0.f, 0.f);
    const __half2* tlane = tin + lane;
    int j0 = beg;
    for (; j0 + 32 <= end; j0 += 32) {
        int s = __ldg(&g_src[j0 + lane]);
#pragma unroll
        for (int t = 0; t < 32; ++t) {
            int ss = __shfl_sync(0xFFFFFFFFu, s, t);
            float2 v = __half22float2(__ldcg(&tlane[ss * 32]));
            acc.x += v.x; acc.y += v.y;
        }
    }
    int n = end - j0;
    if (n > 0) {
        int s = (lane < n) ? __ldg(&g_src[j0 + lane]) : 0;
#pragma unroll 8
        for (int t = 0; t < n; ++t) {
            int ss = __shfl_sync(0xFFFFFFFFu, s, t);
            float2 v = __half22float2(__ldcg(&tlane[ss * 32]));
            acc.x += v.x; acc.y += v.y;
        }
    }
    return acc;
}

__global__ __launch_bounds__(1024, 1) void persist_kernel(float* __restrict__ out) {
    extern __shared__ __align__(16) float2 sh_hidden[];   // [ROWS_PB * 32]
    int b = blockIdx.x;
    int row0 = b * ROWS_PB;
    int row1 = min(N_NODES, row0 + ROWS_PB);
    int nrows = row1 - row0;
    int wid = threadIdx.x >> 5, lane = threadIdx.x & 31;

    // load hidden (= c0*xc) into smem; same warp->row mapping used throughout,
    // so no intra-block sync needed for sh_hidden.
    for (int r = wid; r < nrows; r += 32)
        sh_hidden[r * 32 + lane] = __ldcs(&((const float2*)g_hidden)[(row0 + r) * 32 + lane]);

    for (int d = 1; d <= DORD; ++d) {
        const __half2* tin = (d == 1) ? (const __half2*)g_xc16
                            : ((d & 1) ? (const __half2*)g_h16B : (const __half2*)g_h16A);
        __half2* tout = (d & 1) ? (__half2*)g_h16A : (__half2*)g_h16B;
        float cd = g_coeff[d];
        for (int r = wid; r < nrows; r += 32) {
            int row = row0 + r;
            int beg = __ldg(&g_rowptr[row]);
            int end = __ldg(&g_rowptr[row + 1]);
            float2 acc = row_gather(tin, beg, end, lane);
            float di = __ldg(&g_dinv[row]);
            float txx = -di * acc.x;          // Tx = -dinv * sum(u)
            float txy = -di * acc.y;
            if (d < DORD)                     // u_new = dinv * Tx
                __stcg(&tout[row * 32 + lane], __floats2half2_rn(di * txx, di * txy));
            float2 h = sh_hidden[r * 32 + lane];
            h.x = fmaf(cd, txx, h.x);
            h.y = fmaf(cd, txy, h.y);
            sh_hidden[r * 32 + lane] = h;
        }
        if (d < DORD) grid_barrier();
    }

    // epilogue: out = log_softmax(hidden + xc)
    for (int r = wid; r < nrows; r += 32) {
        int row = row0 + r;
        float2 x = __ldcs(&((const float2*)g_xc)[row * 32 + lane]);
        float2 h = sh_hidden[r * 32 + lane];
        float vx = h.x + x.x, vy = h.y + x.y;
        float m = fmaxf(vx, vy);
#pragma unroll
        for (int o = 16; o; o >>= 1) m = fmaxf(m, __shfl_xor_sync(0xFFFFFFFFu, m, o));
        float s = expf(vx - m) + expf(vy - m);
#pragma unroll
        for (int o = 16; o; o >>= 1) s += __shfl_xor_sync(0xFFFFFFFFu, s, o);
        float l = m + logf(s);
        __stcs(&((float2*)out)[row * 32 + lane], make_float2(vx - l, vy - l));
    }
}

// ---------------- launch ----------------
extern "C" void kernel_launch(void* const* d_in, const int* in_sizes, int n_in,
                              void* d_out, int out_size) {
    const float* feature = (const float*)d_in[0];
    const int*   edges   = (const int*)d_in[1];   // int32
    const float* W1      = (const float*)d_in[2];
    const float* b1      = (const float*)d_in[3];
    const float* W2      = (const float*)d_in[4];
    const float* b2      = (const float*)d_in[5];
    const float* alpha   = (const float*)d_in[6];
    const float* beta    = (const float*)d_in[7];
    float* out           = (float*)d_out;

    // idempotent, host-side, capture-safe; called every time (no static guards)
    cudaFuncSetAttribute(persist_kernel,
                         cudaFuncAttributeMaxDynamicSharedMemorySize, (int)PSMEM);

    const int TB = 256;
    int gN   = (N_NODES + TB - 1) / TB;
    int gE   = (E_EDGES + TB - 1) / TB;
    int gG   = (N_NODES + 63) / 64;
    int nb   = (N_NODES + 1023) / 1024;

    zero_counts_kernel<<<gN, TB>>>();
    coeff_kernel<<<1, 32>>>(alpha, beta);
    pass1_kernel<<<gE, TB>>>(edges);
    dinv_kernel<<<gN, TB>>>();
    scan1_kernel<<<nb, 1024>>>(N_NODES);
    scan2_kernel<<<1, 32>>>(nb);
    scan3_kernel<<<nb, 1024>>>(N_NODES);
    scatter_kernel<<<gE, TB>>>(edges);

    gemm1_kernel<<<gG, TB>>>(feature, W1, b1);
    gemm2_kernel<<<gG, TB>>>(W2, b2);

    persist_kernel<<<PGRID, 1024, PSMEM>>>(out);
}